// round 16
// baseline (speedup 1.0000x reference)
#include <cuda_runtime.h>
#include <cstdint>

#define ND 100000
#define NE 1600000
#define DD 128
#define NG 64
#define LN_EPS 1e-5f

// ---------------- scratch (device globals; no allocation) ----------------
__device__ float g_agg[ND * DD];     // per-node aggregated messages
__device__ float g_h[ND * DD];       // conv MLP output
__device__ float g_stats[2 * 2 * NG];// per-phase: sum[NG], sumsq[NG]
__device__ float g_mi[2 * NG];       // per-graph mean, inv-std (current phase)
__device__ float g_gcnt[NG];         // per-graph element counts (computed once)
// counting-sort-by-dst structures (built once per launch, used by both convs)
__device__ int  g_cnt[ND];           // histogram / scratch
__device__ int  g_ofs[ND + 1];       // CSR offsets
__device__ int  g_cur[ND];           // fill cursors
__device__ int2 g_epk[NE];           // sorted (src, edge_id) pairs

__device__ __forceinline__ uint32_t f2tf(float f) {
    uint32_t r;
    asm("cvt.rna.tf32.f32 %0, %1;" : "=r"(r) : "f"(f));
    return r;
}

__device__ __forceinline__ void mma_tf32(float* c,
                                         uint32_t a0, uint32_t a1, uint32_t a2, uint32_t a3,
                                         uint32_t b0, uint32_t b1) {
    asm volatile("mma.sync.aligned.m16n8k8.row.col.f32.tf32.tf32.f32 "
                 "{%0,%1,%2,%3}, {%4,%5,%6,%7}, {%8,%9}, {%0,%1,%2,%3};"
                 : "+f"(c[0]), "+f"(c[1]), "+f"(c[2]), "+f"(c[3])
                 : "r"(a0), "r"(a1), "r"(a2), "r"(a3), "r"(b0), "r"(b1));
}

// ================= counting sort by dst =================
__global__ void zero_cnt_k() {
    int i = blockIdx.x * blockDim.x + threadIdx.x;
    if (i < ND) g_cnt[i] = 0;
}
__global__ void hist_k(const int* __restrict__ ei) {
    int e = blockIdx.x * blockDim.x + threadIdx.x;
    if (e < NE) atomicAdd(&g_cnt[__ldg(ei + NE + e)], 1);
}
__global__ void scan_k() {
    __shared__ int warp_sums[32];
    const int T = 1024;
    int t = threadIdx.x;
    int chunk = (ND + T - 1) / T;
    int lo = t * chunk, hi = min(lo + chunk, ND);
    int s = 0;
    for (int i = lo; i < hi; i++) s += g_cnt[i];
    int lane = t & 31, w = t >> 5;
    int v = s;
#pragma unroll
    for (int o = 1; o < 32; o <<= 1) {
        int u = __shfl_up_sync(0xFFFFFFFFu, v, o);
        if (lane >= o) v += u;
    }
    if (lane == 31) warp_sums[w] = v;
    __syncthreads();
    if (w == 0) {
        int ws = warp_sums[lane];
#pragma unroll
        for (int o = 1; o < 32; o <<= 1) {
            int u = __shfl_up_sync(0xFFFFFFFFu, ws, o);
            if (lane >= o) ws += u;
        }
        warp_sums[lane] = ws;
    }
    __syncthreads();
    int excl = (v - s) + (w > 0 ? warp_sums[w - 1] : 0);
    int run = excl;
    for (int i = lo; i < hi; i++) {
        int c = g_cnt[i];
        g_ofs[i] = run;
        g_cur[i] = run;
        run += c;
    }
    if (t == T - 1) g_ofs[ND] = run;
}
__global__ void fill_k(const int* __restrict__ ei) {
    int e = blockIdx.x * blockDim.x + threadIdx.x;
    if (e >= NE) return;
    int dst = __ldg(ei + NE + e);
    int src = __ldg(ei + e);
    int pos = atomicAdd(&g_cur[dst], 1);
    g_epk[pos] = make_int2(src, e);
}

// ---------------- per-graph counts (once per launch) + zero both stat phases ----------------
__global__ void count_k(const int* __restrict__ n2g) {
    int i = threadIdx.x;
    if (i < 4 * NG) g_stats[i] = 0.f;
    int g = i;
    if (g >= NG) return;
    auto lb = [&](int val) {
        int lo = 0, hi = ND;
        while (lo < hi) {
            int mid = (lo + hi) >> 1;
            if (__ldg(n2g + mid) < val) lo = mid + 1; else hi = mid;
        }
        return lo;
    };
    int c = lb(g + 1) - lb(g);
    g_gcnt[g] = fmaxf((float)c * (float)DD, 1.f);
}

// ---------------- gather: agg[n] = sum_{e: dst=n} relu(src_feat + ea[e]) ----------------
// one warp per node. use_norm=0: src_feat = x[src]. use_norm=1: src_feat =
// relu(LN(g_h[src])) applied on the fly (norm_relu pass fused away).
__global__ void gather_k(const float* __restrict__ x,
                         const float* __restrict__ ea,
                         const int* __restrict__ n2g,
                         const float* __restrict__ gamma,
                         const float* __restrict__ beta,
                         int use_norm) {
    unsigned gid = blockIdx.x * blockDim.x + threadIdx.x;
    unsigned node = gid >> 5;
    int lane = threadIdx.x & 31;
    if (node >= ND) return;
    const float* xin = use_norm ? g_h : x;
    float4 ga = make_float4(0.f, 0.f, 0.f, 0.f), be = ga;
    if (use_norm) {
        ga = __ldg((const float4*)gamma + lane);
        be = __ldg((const float4*)beta + lane);
    }
    int start = __ldg(g_ofs + node);
    int end = __ldg(g_ofs + node + 1);
    float4 acc = make_float4(0.f, 0.f, 0.f, 0.f);
    for (int j = start; j < end; j++) {
        int2 pk = __ldg(g_epk + j);
        float4 xv = __ldg((const float4*)(xin + (size_t)pk.x * DD) + lane);
        if (use_norm) {
            int g = __ldg(n2g + pk.x);
            float mean = g_mi[g], inv = g_mi[NG + g];
            xv.x = fmaxf((xv.x - mean) * inv * ga.x + be.x, 0.f);
            xv.y = fmaxf((xv.y - mean) * inv * ga.y + be.y, 0.f);
            xv.z = fmaxf((xv.z - mean) * inv * ga.z + be.z, 0.f);
            xv.w = fmaxf((xv.w - mean) * inv * ga.w + be.w, 0.f);
        }
        float4 ev = __ldcs((const float4*)(ea + (size_t)pk.y * DD) + lane);
        acc.x += fmaxf(xv.x + ev.x, 0.f);
        acc.y += fmaxf(xv.y + ev.y, 0.f);
        acc.z += fmaxf(xv.z + ev.z, 0.f);
        acc.w += fmaxf(xv.w + ev.w, 0.f);
    }
    __stcs((float4*)(g_agg + (size_t)node * DD) + lane, acc);   // read-once downstream
}

// ---------------- tf32 mma.sync fused 2-layer MLP ----------------
// CTA: 512 threads, 256-node tile. 16 warps as 4(m) x 4(n); warp tile 64m x 32n.
#define TM 256
#define NT 512
#define SA_STR 132
#define SB_STR 136
#define SA_WORDS (TM * SA_STR)
#define SB_WORDS (128 * SB_STR)
#define MLP_SMEM ((SA_WORDS + SB_WORDS) * 4)

__global__ void __launch_bounds__(NT, 1)
mlp_tc_k(const float* __restrict__ xin_param,
         const float* __restrict__ eps,
         const float* __restrict__ W1, const float* __restrict__ b1,
         const float* __restrict__ W2, const float* __restrict__ b2,
         const int* __restrict__ n2g,
         const float* __restrict__ gamma,
         const float* __restrict__ beta,
         int use_norm) {
    extern __shared__ uint32_t smu[];
    uint32_t* sA = smu;
    uint32_t* sB = smu + SA_WORDS;

    const float* xin = use_norm ? g_h : xin_param;
    int tid = threadIdx.x;
    int wid = tid >> 5;
    int lane = tid & 31;
    int gid = lane >> 2, tig = lane & 3;
    int wm = wid >> 2;          // 0..3
    int wn = wid & 3;           // 0..3
    int n0 = blockIdx.x * TM;
    float epv = 1.f + __ldg(eps);

    // ---- stage A: h = (1+eps)*xfeat + agg (tf32); xfeat optionally LN+relu ----
    for (int i = tid; i < TM * 32; i += NT) {
        int r = i >> 5, c4 = i & 31;
        int n = n0 + r;
        uint4 o = make_uint4(0u, 0u, 0u, 0u);
        if (n < ND) {
            float4 xv = __ldg((const float4*)(xin + (size_t)n * DD) + c4);
            if (use_norm) {
                int g = __ldg(n2g + n);
                float mean = g_mi[g], inv = g_mi[NG + g];
                float4 ga = __ldg((const float4*)gamma + c4);
                float4 be = __ldg((const float4*)beta + c4);
                xv.x = fmaxf((xv.x - mean) * inv * ga.x + be.x, 0.f);
                xv.y = fmaxf((xv.y - mean) * inv * ga.y + be.y, 0.f);
                xv.z = fmaxf((xv.z - mean) * inv * ga.z + be.z, 0.f);
                xv.w = fmaxf((xv.w - mean) * inv * ga.w + be.w, 0.f);
            }
            float4 av = __ldcs((const float4*)(g_agg + (size_t)n * DD) + c4);
            o.x = f2tf(epv * xv.x + av.x);
            o.y = f2tf(epv * xv.y + av.y);
            o.z = f2tf(epv * xv.z + av.z);
            o.w = f2tf(epv * xv.w + av.w);
        }
        *(uint4*)(sA + r * SA_STR + c4 * 4) = o;
    }
    // ---- stage B = W1 [k][n] (tf32) ----
    for (int i = tid; i < 128 * 32; i += NT) {
        int k = i >> 5, c4 = i & 31;
        float4 w = __ldg((const float4*)W1 + i);
        uint4 o;
        o.x = f2tf(w.x); o.y = f2tf(w.y); o.z = f2tf(w.z); o.w = f2tf(w.w);
        *(uint4*)(sB + k * SB_STR + c4 * 4) = o;
    }
    __syncthreads();

    float acc[4][4][4];
#pragma unroll
    for (int mt = 0; mt < 4; mt++)
#pragma unroll
        for (int nt = 0; nt < 4; nt++)
#pragma unroll
            for (int j = 0; j < 4; j++) acc[mt][nt][j] = 0.f;

    // ---- GEMM1 ----
#pragma unroll
    for (int ks = 0; ks < 16; ks++) {
        int k0 = ks * 8;
        uint32_t a[4][4];
#pragma unroll
        for (int mt = 0; mt < 4; mt++) {
            int r0 = wm * 64 + mt * 16 + gid;
            a[mt][0] = sA[r0 * SA_STR + k0 + tig];
            a[mt][1] = sA[(r0 + 8) * SA_STR + k0 + tig];
            a[mt][2] = sA[r0 * SA_STR + k0 + tig + 4];
            a[mt][3] = sA[(r0 + 8) * SA_STR + k0 + tig + 4];
        }
        uint32_t b[4][2];
#pragma unroll
        for (int nt = 0; nt < 4; nt++) {
            int c = wn * 32 + nt * 8 + gid;
            b[nt][0] = sB[(k0 + tig) * SB_STR + c];
            b[nt][1] = sB[(k0 + tig + 4) * SB_STR + c];
        }
#pragma unroll
        for (int mt = 0; mt < 4; mt++)
#pragma unroll
            for (int nt = 0; nt < 4; nt++)
                mma_tf32(acc[mt][nt], a[mt][0], a[mt][1], a[mt][2], a[mt][3],
                         b[nt][0], b[nt][1]);
    }
    __syncthreads();

    // ---- epilogue1: sA[m][n] = tf32(relu(acc + b1[n])); restage sB = W2 ----
#pragma unroll
    for (int mt = 0; mt < 4; mt++) {
        int r0 = wm * 64 + mt * 16 + gid;
#pragma unroll
        for (int nt = 0; nt < 4; nt++) {
            int c = wn * 32 + nt * 8 + 2 * tig;
            float bl0 = __ldg(b1 + c), bl1 = __ldg(b1 + c + 1);
            sA[r0 * SA_STR + c]           = f2tf(fmaxf(acc[mt][nt][0] + bl0, 0.f));
            sA[r0 * SA_STR + c + 1]       = f2tf(fmaxf(acc[mt][nt][1] + bl1, 0.f));
            sA[(r0 + 8) * SA_STR + c]     = f2tf(fmaxf(acc[mt][nt][2] + bl0, 0.f));
            sA[(r0 + 8) * SA_STR + c + 1] = f2tf(fmaxf(acc[mt][nt][3] + bl1, 0.f));
#pragma unroll
            for (int j = 0; j < 4; j++) acc[mt][nt][j] = 0.f;
        }
    }
    for (int i = tid; i < 128 * 32; i += NT) {
        int k = i >> 5, c4 = i & 31;
        float4 w = __ldg((const float4*)W2 + i);
        uint4 o;
        o.x = f2tf(w.x); o.y = f2tf(w.y); o.z = f2tf(w.z); o.w = f2tf(w.w);
        *(uint4*)(sB + k * SB_STR + c4 * 4) = o;
    }
    __syncthreads();

    // ---- GEMM2 ----
#pragma unroll
    for (int ks = 0; ks < 16; ks++) {
        int k0 = ks * 8;
        uint32_t a[4][4];
#pragma unroll
        for (int mt = 0; mt < 4; mt++) {
            int r0 = wm * 64 + mt * 16 + gid;
            a[mt][0] = sA[r0 * SA_STR + k0 + tig];
            a[mt][1] = sA[(r0 + 8) * SA_STR + k0 + tig];
            a[mt][2] = sA[r0 * SA_STR + k0 + tig + 4];
            a[mt][3] = sA[(r0 + 8) * SA_STR + k0 + tig + 4];
        }
        uint32_t b[4][2];
#pragma unroll
        for (int nt = 0; nt < 4; nt++) {
            int c = wn * 32 + nt * 8 + gid;
            b[nt][0] = sB[(k0 + tig) * SB_STR + c];
            b[nt][1] = sB[(k0 + tig + 4) * SB_STR + c];
        }
#pragma unroll
        for (int mt = 0; mt < 4; mt++)
#pragma unroll
            for (int nt = 0; nt < 4; nt++)
                mma_tf32(acc[mt][nt], a[mt][0], a[mt][1], a[mt][2], a[mt][3],
                         b[nt][0], b[nt][1]);
    }

    // ---- epilogue2: g_h = acc + b2 ----
#pragma unroll
    for (int mt = 0; mt < 4; mt++) {
        int r0 = wm * 64 + mt * 16 + gid;
        int na = n0 + r0, nb = na + 8;
#pragma unroll
        for (int nt = 0; nt < 4; nt++) {
            int c = wn * 32 + nt * 8 + 2 * tig;
            float bl0 = __ldg(b2 + c), bl1 = __ldg(b2 + c + 1);
            if (na < ND) {
                float2 v = make_float2(acc[mt][nt][0] + bl0, acc[mt][nt][1] + bl1);
                *(float2*)(g_h + (size_t)na * DD + c) = v;
            }
            if (nb < ND) {
                float2 v = make_float2(acc[mt][nt][2] + bl0, acc[mt][nt][3] + bl1);
                *(float2*)(g_h + (size_t)nb * DD + c) = v;
            }
        }
    }
}

// ---------------- per-graph stats: warp per node ----------------
__global__ void stats_k(const int* __restrict__ n2g, int phase) {
    unsigned gid = blockIdx.x * blockDim.x + threadIdx.x;
    unsigned node = gid >> 5;
    int lane = threadIdx.x & 31;
    if (node >= ND) return;
    float4 v = *((const float4*)(g_h + (size_t)node * DD) + lane);
    float s = v.x + v.y + v.z + v.w;
    float q = v.x * v.x + v.y * v.y + v.z * v.z + v.w * v.w;
#pragma unroll
    for (int o = 16; o; o >>= 1) {
        s += __shfl_xor_sync(0xFFFFFFFFu, s, o);
        q += __shfl_xor_sync(0xFFFFFFFFu, q, o);
    }
    if (lane == 0) {
        int g = __ldg(n2g + node);
        float* st = g_stats + phase * 2 * NG;
        atomicAdd(st + g, s);
        atomicAdd(st + NG + g, q);
    }
}

// ---------------- finalize: lean (counts precomputed) ----------------
__global__ void finalize_k(int phase) {
    int g = threadIdx.x;
    if (g >= NG) return;
    const float* st = g_stats + phase * 2 * NG;
    float cnt = g_gcnt[g];
    float mean = st[g] / cnt;
    float var = st[NG + g] / cnt - mean * mean;
    g_mi[g] = mean;
    g_mi[NG + g] = rsqrtf(var + LN_EPS);
}

// ---------------- final: out = relu((LN2(h2) + x) * 0.5) ----------------
__global__ void final_k(const int* __restrict__ n2g,
                        const float* __restrict__ gamma,
                        const float* __restrict__ beta,
                        const float* __restrict__ x,
                        float* __restrict__ out) {
    unsigned i = blockIdx.x * blockDim.x + threadIdx.x;
    if (i >= ND * 32u) return;
    unsigned node = i >> 5;
    int c4 = i & 31;
    int g = __ldg(n2g + node);
    float mean = g_mi[g], inv = g_mi[NG + g];
    float4 v = ((const float4*)g_h)[i];
    float4 xv = __ldg((const float4*)x + i);
    float4 ga = __ldg((const float4*)gamma + c4);
    float4 be = __ldg((const float4*)beta + c4);
    float4 o;
    o.x = fmaxf(((v.x - mean) * inv * ga.x + be.x + xv.x) * 0.5f, 0.f);
    o.y = fmaxf(((v.y - mean) * inv * ga.y + be.y + xv.y) * 0.5f, 0.f);
    o.z = fmaxf(((v.z - mean) * inv * ga.z + be.z + xv.z) * 0.5f, 0.f);
    o.w = fmaxf(((v.w - mean) * inv * ga.w + be.w + xv.w) * 0.5f, 0.f);
    ((float4*)out)[i] = o;
}

// ---------------- launch ----------------
extern "C" void kernel_launch(void* const* d_in, const int* in_sizes, int n_in,
                              void* d_out, int out_size) {
    const float* x   = (const float*)d_in[0];
    const int*   ei  = (const int*)d_in[1];
    const float* ea  = (const float*)d_in[2];
    const int*   n2g = (const int*)d_in[3];
    const float* eps1 = (const float*)d_in[4];
    const float* eps2 = (const float*)d_in[5];
    const float* W1a = (const float*)d_in[6];  const float* b1a = (const float*)d_in[7];
    const float* W2a = (const float*)d_in[8];  const float* b2a = (const float*)d_in[9];
    const float* W1b = (const float*)d_in[10]; const float* b1b = (const float*)d_in[11];
    const float* W2b = (const float*)d_in[12]; const float* b2b = (const float*)d_in[13];
    const float* g1  = (const float*)d_in[14]; const float* bt1 = (const float*)d_in[15];
    const float* g2  = (const float*)d_in[16]; const float* bt2 = (const float*)d_in[17];
    float* out = (float*)d_out;

    cudaFuncSetAttribute(mlp_tc_k, cudaFuncAttributeMaxDynamicSharedMemorySize, MLP_SMEM);

    const int EB = (NE + 255) / 256;         // 6250
    const int GB = (ND * 32 + 255) / 256;    // warp-per-node gather
    const int MB = (ND + TM - 1) / TM;       // 391
    const int NB = (ND * 32) / 256;          // 12500

    // ---- build dst-sorted edge list + per-graph counts ----
    zero_cnt_k<<<(ND + 255) / 256, 256>>>();
    hist_k<<<EB, 256>>>(ei);
    scan_k<<<1, 1024>>>();
    fill_k<<<EB, 256>>>(ei);
    count_k<<<1, 256>>>(n2g);

    // ---- conv1 ----
    gather_k<<<GB, 256>>>(x, ea, n2g, g1, bt1, 0);
    mlp_tc_k<<<MB, NT, MLP_SMEM>>>(x, eps1, W1a, b1a, W2a, b2a, n2g, g1, bt1, 0);
    // ---- LN1 stats (normalization applied on the fly by conv2 consumers) ----
    stats_k<<<NB, 256>>>(n2g, 0);
    finalize_k<<<1, 64>>>(0);
    // ---- conv2: gather + MLP read g_h and apply LN1+relu inline ----
    gather_k<<<GB, 256>>>(x, ea, n2g, g1, bt1, 1);
    mlp_tc_k<<<MB, NT, MLP_SMEM>>>(x, eps2, W1b, b1b, W2b, b2b, n2g, g1, bt1, 1);
    // ---- LN2 + residual + relu ----
    stats_k<<<NB, 256>>>(n2g, 1);
    finalize_k<<<1, 64>>>(1);
    final_k<<<NB, 256>>>(n2g, g2, bt2, x, out);
}

// round 17
// speedup vs baseline: 1.1507x; 1.1507x over previous
#include <cuda_runtime.h>
#include <cuda_fp16.h>
#include <cstdint>

#define ND 100000
#define NE 1600000
#define DD 128
#define NG 64
#define LN_EPS 1e-5f

// ---------------- scratch (device globals; no allocation) ----------------
__device__ float g_agg[ND * DD];     // per-node aggregated messages
__device__ float g_h[ND * DD];       // conv MLP output
__device__ float g_x1[ND * DD];      // relu(LN1(conv1))
__device__ float g_stats[2 * 2 * NG];// per-phase: sum[NG], sumsq[NG]
__device__ float g_mi[2 * NG];       // per-graph mean, inv-std
__device__ float g_gcnt[NG];         // per-graph element counts (computed once)
// counting-sort-by-dst structures (built once per launch, used by both convs)
__device__ int  g_cnt[ND];           // histogram / scratch
__device__ int  g_ofs[ND + 1];       // CSR offsets
__device__ int  g_cur[ND];           // fill cursors
__device__ int2 g_epk[NE];           // sorted (src, edge_id) pairs

__device__ __forceinline__ uint32_t pack_h2(float a, float b) {
    __half2 h = __floats2half2_rn(a, b);
    return *(uint32_t*)&h;
}

__device__ __forceinline__ void mma_f16(float* c,
                                        uint32_t a0, uint32_t a1, uint32_t a2, uint32_t a3,
                                        uint32_t b0, uint32_t b1) {
    asm volatile("mma.sync.aligned.m16n8k16.row.col.f32.f16.f16.f32 "
                 "{%0,%1,%2,%3}, {%4,%5,%6,%7}, {%8,%9}, {%0,%1,%2,%3};"
                 : "+f"(c[0]), "+f"(c[1]), "+f"(c[2]), "+f"(c[3])
                 : "r"(a0), "r"(a1), "r"(a2), "r"(a3), "r"(b0), "r"(b1));
}

// ================= counting sort by dst =================
__global__ void zero_cnt_k() {
    int i = blockIdx.x * blockDim.x + threadIdx.x;
    if (i < ND) g_cnt[i] = 0;
}
__global__ void hist_k(const int* __restrict__ ei) {
    int e = blockIdx.x * blockDim.x + threadIdx.x;
    if (e < NE) atomicAdd(&g_cnt[__ldg(ei + NE + e)], 1);
}
__global__ void scan_k() {
    __shared__ int warp_sums[32];
    const int T = 1024;
    int t = threadIdx.x;
    int chunk = (ND + T - 1) / T;
    int lo = t * chunk, hi = min(lo + chunk, ND);
    int s = 0;
    for (int i = lo; i < hi; i++) s += g_cnt[i];
    int lane = t & 31, w = t >> 5;
    int v = s;
#pragma unroll
    for (int o = 1; o < 32; o <<= 1) {
        int u = __shfl_up_sync(0xFFFFFFFFu, v, o);
        if (lane >= o) v += u;
    }
    if (lane == 31) warp_sums[w] = v;
    __syncthreads();
    if (w == 0) {
        int ws = warp_sums[lane];
#pragma unroll
        for (int o = 1; o < 32; o <<= 1) {
            int u = __shfl_up_sync(0xFFFFFFFFu, ws, o);
            if (lane >= o) ws += u;
        }
        warp_sums[lane] = ws;
    }
    __syncthreads();
    int excl = (v - s) + (w > 0 ? warp_sums[w - 1] : 0);
    int run = excl;
    for (int i = lo; i < hi; i++) {
        int c = g_cnt[i];
        g_ofs[i] = run;
        g_cur[i] = run;
        run += c;
    }
    if (t == T - 1) g_ofs[ND] = run;
}
__global__ void fill_k(const int* __restrict__ ei) {
    int e = blockIdx.x * blockDim.x + threadIdx.x;
    if (e >= NE) return;
    int dst = __ldg(ei + NE + e);
    int src = __ldg(ei + e);
    int pos = atomicAdd(&g_cur[dst], 1);
    g_epk[pos] = make_int2(src, e);
}

// ---------------- per-graph counts (once per launch) + zero both stat phases ----------------
__global__ void count_k(const int* __restrict__ n2g) {
    int i = threadIdx.x;
    if (i < 4 * NG) g_stats[i] = 0.f;
    int g = i;
    if (g >= NG) return;
    auto lb = [&](int val) {
        int lo = 0, hi = ND;
        while (lo < hi) {
            int mid = (lo + hi) >> 1;
            if (__ldg(n2g + mid) < val) lo = mid + 1; else hi = mid;
        }
        return lo;
    };
    int c = lb(g + 1) - lb(g);
    g_gcnt[g] = fmaxf((float)c * (float)DD, 1.f);
}

// ---------------- gather: agg[n] = sum_{e: dst=n} relu(x[src] + ea[e]) ----------------
// one warp per node; simple loop (proven fastest)
__global__ void gather_k(const float* __restrict__ x,
                         const float* __restrict__ ea,
                         int use_x1) {
    unsigned gid = blockIdx.x * blockDim.x + threadIdx.x;
    unsigned node = gid >> 5;
    int lane = threadIdx.x & 31;
    if (node >= ND) return;
    const float* xin = use_x1 ? g_x1 : x;
    int start = __ldg(g_ofs + node);
    int end = __ldg(g_ofs + node + 1);
    float4 acc = make_float4(0.f, 0.f, 0.f, 0.f);
    for (int j = start; j < end; j++) {
        int2 pk = __ldg(g_epk + j);
        float4 xv = __ldg((const float4*)(xin + (size_t)pk.x * DD) + lane);
        float4 ev = __ldcs((const float4*)(ea + (size_t)pk.y * DD) + lane);
        acc.x += fmaxf(xv.x + ev.x, 0.f);
        acc.y += fmaxf(xv.y + ev.y, 0.f);
        acc.z += fmaxf(xv.z + ev.z, 0.f);
        acc.w += fmaxf(xv.w + ev.w, 0.f);
    }
    __stcs((float4*)(g_agg + (size_t)node * DD) + lane, acc);   // read-once downstream
}

// ---------------- fp16 mma.sync fused 2-layer MLP ----------------
// CTA: 512 threads, 256-node tile. 16 warps as 4(m) x 4(n); warp tile 64m x 32n.
// sA: [256 m][68 half2-words] (64 used = 128 fp16 along k; stride 68 -> 4*gid+tig banks)
// sB: [128 n][68 half2-words] (k-contiguous per n row -> b-frags are half2 loads)
#define TM 256
#define NT 512
#define SA_STR 68
#define SB_STR 68
#define SA_WORDS (TM * SA_STR)
#define SB_WORDS (128 * SB_STR)
#define MLP_SMEM ((SA_WORDS + SB_WORDS) * 4)

__global__ void __launch_bounds__(NT, 1)
mlp_tc_k(const float* __restrict__ xin_param,
         const float* __restrict__ eps,
         const float* __restrict__ W1, const float* __restrict__ b1,
         const float* __restrict__ W2, const float* __restrict__ b2,
         int use_x1) {
    extern __shared__ uint32_t smu[];
    uint32_t* sA = smu;
    uint32_t* sB = smu + SA_WORDS;
    __half* sBh = (__half*)sB;

    const float* xin = use_x1 ? g_x1 : xin_param;
    int tid = threadIdx.x;
    int wid = tid >> 5;
    int lane = tid & 31;
    int gid = lane >> 2, tig = lane & 3;
    int wm = wid >> 2;          // 0..3
    int wn = wid & 3;           // 0..3
    int n0 = blockIdx.x * TM;
    float epv = 1.f + __ldg(eps);

    // ---- stage A: h = (1+eps)*x + agg (fp16) ----
    for (int i = tid; i < TM * 32; i += NT) {
        int r = i >> 5, c4 = i & 31;
        int n = n0 + r;
        uint2 o = make_uint2(0u, 0u);
        if (n < ND) {
            float4 xv = __ldg((const float4*)(xin + (size_t)n * DD) + c4);
            float4 av = __ldcs((const float4*)(g_agg + (size_t)n * DD) + c4);
            o.x = pack_h2(epv * xv.x + av.x, epv * xv.y + av.y);
            o.y = pack_h2(epv * xv.z + av.z, epv * xv.w + av.w);
        }
        *(uint2*)(sA + r * SA_STR + c4 * 2) = o;
    }
    // ---- stage B[n][k] = W1[k][n] (fp16, transposed scatter) ----
    for (int i = tid; i < 128 * 32; i += NT) {
        int k = i >> 5, n4 = (i & 31) * 4;
        float4 w = __ldg((const float4*)W1 + i);
        sBh[(n4 + 0) * (2 * SB_STR) + k] = __float2half_rn(w.x);
        sBh[(n4 + 1) * (2 * SB_STR) + k] = __float2half_rn(w.y);
        sBh[(n4 + 2) * (2 * SB_STR) + k] = __float2half_rn(w.z);
        sBh[(n4 + 3) * (2 * SB_STR) + k] = __float2half_rn(w.w);
    }
    __syncthreads();

    float acc[4][4][4];
#pragma unroll
    for (int mt = 0; mt < 4; mt++)
#pragma unroll
        for (int nt = 0; nt < 4; nt++)
#pragma unroll
            for (int j = 0; j < 4; j++) acc[mt][nt][j] = 0.f;

    // ---- GEMM1 (8 K-steps of 16) ----
#pragma unroll
    for (int ks = 0; ks < 8; ks++) {
        int kw0 = ks * 8;
        uint32_t a[4][4];
#pragma unroll
        for (int mt = 0; mt < 4; mt++) {
            int r0 = wm * 64 + mt * 16 + gid;
            a[mt][0] = sA[r0 * SA_STR + kw0 + tig];
            a[mt][1] = sA[(r0 + 8) * SA_STR + kw0 + tig];
            a[mt][2] = sA[r0 * SA_STR + kw0 + tig + 4];
            a[mt][3] = sA[(r0 + 8) * SA_STR + kw0 + tig + 4];
        }
        uint32_t b[4][2];
#pragma unroll
        for (int nt = 0; nt < 4; nt++) {
            int c = wn * 32 + nt * 8 + gid;
            b[nt][0] = sB[c * SB_STR + kw0 + tig];
            b[nt][1] = sB[c * SB_STR + kw0 + tig + 4];
        }
#pragma unroll
        for (int mt = 0; mt < 4; mt++)
#pragma unroll
            for (int nt = 0; nt < 4; nt++)
                mma_f16(acc[mt][nt], a[mt][0], a[mt][1], a[mt][2], a[mt][3],
                        b[nt][0], b[nt][1]);
    }
    __syncthreads();

    // ---- epilogue1: sA[m][n] = fp16(relu(acc + b1[n])); restage sB = W2 ----
#pragma unroll
    for (int mt = 0; mt < 4; mt++) {
        int r0 = wm * 64 + mt * 16 + gid;
#pragma unroll
        for (int nt = 0; nt < 4; nt++) {
            int c = wn * 32 + nt * 8 + 2 * tig;
            int cw = wn * 16 + nt * 4 + tig;           // half2 word index = c/2
            float bl0 = __ldg(b1 + c), bl1 = __ldg(b1 + c + 1);
            sA[r0 * SA_STR + cw] =
                pack_h2(fmaxf(acc[mt][nt][0] + bl0, 0.f), fmaxf(acc[mt][nt][1] + bl1, 0.f));
            sA[(r0 + 8) * SA_STR + cw] =
                pack_h2(fmaxf(acc[mt][nt][2] + bl0, 0.f), fmaxf(acc[mt][nt][3] + bl1, 0.f));
#pragma unroll
            for (int j = 0; j < 4; j++) acc[mt][nt][j] = 0.f;
        }
    }
    for (int i = tid; i < 128 * 32; i += NT) {
        int k = i >> 5, n4 = (i & 31) * 4;
        float4 w = __ldg((const float4*)W2 + i);
        sBh[(n4 + 0) * (2 * SB_STR) + k] = __float2half_rn(w.x);
        sBh[(n4 + 1) * (2 * SB_STR) + k] = __float2half_rn(w.y);
        sBh[(n4 + 2) * (2 * SB_STR) + k] = __float2half_rn(w.z);
        sBh[(n4 + 3) * (2 * SB_STR) + k] = __float2half_rn(w.w);
    }
    __syncthreads();

    // ---- GEMM2 ----
#pragma unroll
    for (int ks = 0; ks < 8; ks++) {
        int kw0 = ks * 8;
        uint32_t a[4][4];
#pragma unroll
        for (int mt = 0; mt < 4; mt++) {
            int r0 = wm * 64 + mt * 16 + gid;
            a[mt][0] = sA[r0 * SA_STR + kw0 + tig];
            a[mt][1] = sA[(r0 + 8) * SA_STR + kw0 + tig];
            a[mt][2] = sA[r0 * SA_STR + kw0 + tig + 4];
            a[mt][3] = sA[(r0 + 8) * SA_STR + kw0 + tig + 4];
        }
        uint32_t b[4][2];
#pragma unroll
        for (int nt = 0; nt < 4; nt++) {
            int c = wn * 32 + nt * 8 + gid;
            b[nt][0] = sB[c * SB_STR + kw0 + tig];
            b[nt][1] = sB[c * SB_STR + kw0 + tig + 4];
        }
#pragma unroll
        for (int mt = 0; mt < 4; mt++)
#pragma unroll
            for (int nt = 0; nt < 4; nt++)
                mma_f16(acc[mt][nt], a[mt][0], a[mt][1], a[mt][2], a[mt][3],
                        b[nt][0], b[nt][1]);
    }

    // ---- epilogue2: g_h = acc + b2 ----
#pragma unroll
    for (int mt = 0; mt < 4; mt++) {
        int r0 = wm * 64 + mt * 16 + gid;
        int na = n0 + r0, nb = na + 8;
#pragma unroll
        for (int nt = 0; nt < 4; nt++) {
            int c = wn * 32 + nt * 8 + 2 * tig;
            float bl0 = __ldg(b2 + c), bl1 = __ldg(b2 + c + 1);
            if (na < ND) {
                float2 v = make_float2(acc[mt][nt][0] + bl0, acc[mt][nt][1] + bl1);
                *(float2*)(g_h + (size_t)na * DD + c) = v;
            }
            if (nb < ND) {
                float2 v = make_float2(acc[mt][nt][2] + bl0, acc[mt][nt][3] + bl1);
                *(float2*)(g_h + (size_t)nb * DD + c) = v;
            }
        }
    }
}

// ---------------- per-graph stats: warp per node ----------------
__global__ void stats_k(const int* __restrict__ n2g, int phase) {
    unsigned gid = blockIdx.x * blockDim.x + threadIdx.x;
    unsigned node = gid >> 5;
    int lane = threadIdx.x & 31;
    if (node >= ND) return;
    float4 v = *((const float4*)(g_h + (size_t)node * DD) + lane);
    float s = v.x + v.y + v.z + v.w;
    float q = v.x * v.x + v.y * v.y + v.z * v.z + v.w * v.w;
#pragma unroll
    for (int o = 16; o; o >>= 1) {
        s += __shfl_xor_sync(0xFFFFFFFFu, s, o);
        q += __shfl_xor_sync(0xFFFFFFFFu, q, o);
    }
    if (lane == 0) {
        int g = __ldg(n2g + node);
        float* st = g_stats + phase * 2 * NG;
        atomicAdd(st + g, s);
        atomicAdd(st + NG + g, q);
    }
}

// ---------------- finalize: lean (counts precomputed) ----------------
__global__ void finalize_k(int phase) {
    int g = threadIdx.x;
    if (g >= NG) return;
    const float* st = g_stats + phase * 2 * NG;
    float cnt = g_gcnt[g];
    float mean = st[g] / cnt;
    float var = st[NG + g] / cnt - mean * mean;
    g_mi[g] = mean;
    g_mi[NG + g] = rsqrtf(var + LN_EPS);
}

// ---------------- normalize + relu -> g_x1 ----------------
__global__ void norm_relu_k(const int* __restrict__ n2g,
                            const float* __restrict__ gamma,
                            const float* __restrict__ beta) {
    unsigned i = blockIdx.x * blockDim.x + threadIdx.x;
    if (i >= ND * 32u) return;
    unsigned node = i >> 5;
    int c4 = i & 31;
    int g = __ldg(n2g + node);
    float mean = g_mi[g], inv = g_mi[NG + g];
    float4 v = ((const float4*)g_h)[i];
    float4 ga = __ldg((const float4*)gamma + c4);
    float4 be = __ldg((const float4*)beta + c4);
    float4 o;
    o.x = fmaxf((v.x - mean) * inv * ga.x + be.x, 0.f);
    o.y = fmaxf((v.y - mean) * inv * ga.y + be.y, 0.f);
    o.z = fmaxf((v.z - mean) * inv * ga.z + be.z, 0.f);
    o.w = fmaxf((v.w - mean) * inv * ga.w + be.w, 0.f);
    ((float4*)g_x1)[i] = o;
}

// ---------------- final: out = relu((LN2(h2) + x) * 0.5) ----------------
__global__ void final_k(const int* __restrict__ n2g,
                        const float* __restrict__ gamma,
                        const float* __restrict__ beta,
                        const float* __restrict__ x,
                        float* __restrict__ out) {
    unsigned i = blockIdx.x * blockDim.x + threadIdx.x;
    if (i >= ND * 32u) return;
    unsigned node = i >> 5;
    int c4 = i & 31;
    int g = __ldg(n2g + node);
    float mean = g_mi[g], inv = g_mi[NG + g];
    float4 v = ((const float4*)g_h)[i];
    float4 xv = __ldg((const float4*)x + i);
    float4 ga = __ldg((const float4*)gamma + c4);
    float4 be = __ldg((const float4*)beta + c4);
    float4 o;
    o.x = fmaxf(((v.x - mean) * inv * ga.x + be.x + xv.x) * 0.5f, 0.f);
    o.y = fmaxf(((v.y - mean) * inv * ga.y + be.y + xv.y) * 0.5f, 0.f);
    o.z = fmaxf(((v.z - mean) * inv * ga.z + be.z + xv.z) * 0.5f, 0.f);
    o.w = fmaxf(((v.w - mean) * inv * ga.w + be.w + xv.w) * 0.5f, 0.f);
    ((float4*)out)[i] = o;
}

// ---------------- launch ----------------
extern "C" void kernel_launch(void* const* d_in, const int* in_sizes, int n_in,
                              void* d_out, int out_size) {
    const float* x   = (const float*)d_in[0];
    const int*   ei  = (const int*)d_in[1];
    const float* ea  = (const float*)d_in[2];
    const int*   n2g = (const int*)d_in[3];
    const float* eps1 = (const float*)d_in[4];
    const float* eps2 = (const float*)d_in[5];
    const float* W1a = (const float*)d_in[6];  const float* b1a = (const float*)d_in[7];
    const float* W2a = (const float*)d_in[8];  const float* b2a = (const float*)d_in[9];
    const float* W1b = (const float*)d_in[10]; const float* b1b = (const float*)d_in[11];
    const float* W2b = (const float*)d_in[12]; const float* b2b = (const float*)d_in[13];
    const float* g1  = (const float*)d_in[14]; const float* bt1 = (const float*)d_in[15];
    const float* g2  = (const float*)d_in[16]; const float* bt2 = (const float*)d_in[17];
    float* out = (float*)d_out;

    cudaFuncSetAttribute(mlp_tc_k, cudaFuncAttributeMaxDynamicSharedMemorySize, MLP_SMEM);

    const int EB = (NE + 255) / 256;         // 6250
    const int GB = (ND * 32 + 255) / 256;    // warp-per-node gather
    const int MB = (ND + TM - 1) / TM;       // 391
    const int NB = (ND * 32) / 256;          // 12500

    // ---- build dst-sorted edge list + per-graph counts ----
    zero_cnt_k<<<(ND + 255) / 256, 256>>>();
    hist_k<<<EB, 256>>>(ei);
    scan_k<<<1, 1024>>>();
    fill_k<<<EB, 256>>>(ei);
    count_k<<<1, 256>>>(n2g);

    // ---- conv1 ----
    gather_k<<<GB, 256>>>(x, ea, 0);
    mlp_tc_k<<<MB, NT, MLP_SMEM>>>(x, eps1, W1a, b1a, W2a, b2a, 0);
    // ---- LN1 + relu ----
    stats_k<<<NB, 256>>>(n2g, 0);
    finalize_k<<<1, 64>>>(0);
    norm_relu_k<<<NB, 256>>>(n2g, g1, bt1);
    // ---- conv2 ----
    gather_k<<<GB, 256>>>(x, ea, 1);
    mlp_tc_k<<<MB, NT, MLP_SMEM>>>(x, eps2, W1b, b1b, W2b, b2b, 1);
    // ---- LN2 + residual + relu ----
    stats_k<<<NB, 256>>>(n2g, 1);
    finalize_k<<<1, 64>>>(1);
    final_k<<<NB, 256>>>(n2g, g2, bt2, x, out);
}